// round 5
// baseline (speedup 1.0000x reference)
#include <cuda_runtime.h>
#include <cstddef>

// router_20091857011524: fused 4-way router (GB300 sm_103a) — R5 (= R4 rerun)
// R3 + software pipelining: chunk c+1's global loads (m + W slices) are
// issued into registers BEFORE phase-B compute of chunk c, hiding DRAM
// latency behind the LDS/FMA phase instead of exposing it at each barrier.
// (R4 bench was an infra failure; this is the same design, with the mats[]
// pointer array passed as individual pointers to avoid any spill risk.)

#define THREADS 256
#define TPB_TOK 32
#define CHUNK   64
#define NCHUNK  8

// smem layout (floats):
//   xs   : [4][32][68]  = 8704   (stride 68: 16B-aligned + conflict-free)
//   wsm  : [64][9] f4   = 2304
//   slog : [8*32][9]    = 2304
//   sw   : [32][4]      =  128
#define SM_OFF_W    8704
#define SM_OFF_SLOG 11008
#define SM_OFF_SW   13312
#define SMEM_FLOATS 13440
#define SMEM_BYTES  (SMEM_FLOATS * 4)

struct Pref {
    float4 v[4][2];   // m prefetch: 4 mats x 2 float4
    float4 wv[2];     // W prefetch: 2 reps
};

__device__ __forceinline__
void load_chunk(const float* __restrict__ m0, const float* __restrict__ m1,
                const float* __restrict__ m2, const float* __restrict__ m3,
                const float4* __restrict__ wt4, const float4* __restrict__ ws4,
                size_t rowOff, int jA, int tid, int c, Pref& p)
{
    const int d0 = c * CHUNK;
    const float* mk0 = m0 + rowOff + d0;
    const float* mk1 = m1 + rowOff + d0;
    const float* mk2 = m2 + rowOff + d0;
    const float* mk3 = m3 + rowOff + d0;
    #pragma unroll
    for (int r = 0; r < 2; r++) {
        const int off = 4 * (jA + 8 * r);
        p.v[0][r] = *reinterpret_cast<const float4*>(mk0 + off);
        p.v[1][r] = *reinterpret_cast<const float4*>(mk1 + off);
        p.v[2][r] = *reinterpret_cast<const float4*>(mk2 + off);
        p.v[3][r] = *reinterpret_cast<const float4*>(mk3 + off);
    }
    #pragma unroll
    for (int rep = 0; rep < 2; rep++) {
        const int i  = tid + rep * 256;   // 0..511
        const int o  = i >> 6;            // 0..7
        const int dd = i & 63;            // 0..63
        p.wv[rep] = (o < 4) ? __ldg(wt4 + o * 512 + d0 + dd)
                            : __ldg(ws4 + (o - 4) * 512 + d0 + dd);
    }
}

__global__ __launch_bounds__(THREADS, 4)
void router_kernel(const float* __restrict__ m0, const float* __restrict__ m1,
                   const float* __restrict__ m2, const float* __restrict__ m3,
                   const float* __restrict__ Wt, const float* __restrict__ bt,
                   const float* __restrict__ Ws, const float* __restrict__ bs,
                   const float* __restrict__ alpha, float* __restrict__ out)
{
    extern __shared__ float smem[];
    float*  xs   = smem;
    float4* wsm4 = reinterpret_cast<float4*>(smem + SM_OFF_W);
    float*  slog = smem + SM_OFF_SLOG;
    float*  sw   = smem + SM_OFF_SW;

    const int tokBase = blockIdx.x * TPB_TOK;
    const int tid  = threadIdx.x;
    const int lane = tid & 31;
    const int wrp  = tid >> 5;
    const int tokA = tid >> 3;     // 0..31 (phase A/C token)
    const int jA   = tid & 7;      // 0..7  (phase A/C inner slot)
    const size_t rowOffA = (size_t)(tokBase + tokA) * 512;

    float acc[8];
    #pragma unroll
    for (int o = 0; o < 8; o++) acc[o] = 0.f;

    const float4* wt4 = reinterpret_cast<const float4*>(Wt);  // [4][512] float4
    const float4* ws4 = reinterpret_cast<const float4*>(Ws);
    const float4* xs4 = reinterpret_cast<const float4*>(xs);

    Pref p;
    load_chunk(m0, m1, m2, m3, wt4, ws4, rowOffA, jA, tid, 0, p);

    for (int c = 0; c < NCHUNK; c++) {
        // ---- commit prefetched chunk to SMEM
        #pragma unroll
        for (int k = 0; k < 4; k++) {
            float* s = xs + k * (32 * 68) + tokA * 68;
            #pragma unroll
            for (int r = 0; r < 2; r++)
                *reinterpret_cast<float4*>(s + 4 * (jA + 8 * r)) = p.v[k][r];
        }
        #pragma unroll
        for (int rep = 0; rep < 2; rep++) {
            const int i  = tid + rep * 256;
            const int o  = i >> 6;
            const int dd = i & 63;
            wsm4[dd * 9 + o] = p.wv[rep];
        }
        __syncthreads();

        // ---- issue next chunk's global loads NOW (overlap with compute)
        if (c + 1 < NCHUNK)
            load_chunk(m0, m1, m2, m3, wt4, ws4, rowOffA, jA, tid, c + 1, p);

        // ---- Phase B: lane = token; warp owns dims [wrp*8, wrp*8+8) of chunk
        #pragma unroll
        for (int g = 0; g < 2; g++) {
            const int dc = wrp * 2 + g;                 // float4-group in chunk (0..15)
            float4 x0 = xs4[0 * 544 + lane * 17 + dc];
            float4 x1 = xs4[1 * 544 + lane * 17 + dc];
            float4 x2 = xs4[2 * 544 + lane * 17 + dc];
            float4 x3 = xs4[3 * 544 + lane * 17 + dc];
            const float* xf0 = reinterpret_cast<const float*>(&x0);
            const float* xf1 = reinterpret_cast<const float*>(&x1);
            const float* xf2 = reinterpret_cast<const float*>(&x2);
            const float* xf3 = reinterpret_cast<const float*>(&x3);
            const int dloc = (wrp * 8 + g * 4);
            #pragma unroll
            for (int j = 0; j < 4; j++) {
                #pragma unroll
                for (int o = 0; o < 8; o++) {
                    float4 w = wsm4[(dloc + j) * 9 + o];   // warp-uniform broadcast
                    acc[o] += xf0[j] * w.x + xf1[j] * w.y + xf2[j] * w.z + xf3[j] * w.w;
                }
            }
        }
        __syncthreads();   // everyone done reading smem before next commit
    }

    // ---- write partial logits, reduce across the 8 warps
    {
        float* sl = slog + (wrp * 32 + lane) * 9;
        #pragma unroll
        for (int o = 0; o < 8; o++) sl[o] = acc[o];
    }
    __syncthreads();

    // ---- per-token epilogue (one lane per token, warp 0)
    if (tid < 32) {
        const int tok = tid;
        float lt[4], ls[4];
        #pragma unroll
        for (int kp = 0; kp < 4; kp++) { lt[kp] = __ldg(bt + kp); ls[kp] = __ldg(bs + kp); }
        #pragma unroll
        for (int w2 = 0; w2 < 8; w2++) {
            const float* pp = slog + (w2 * 32 + tok) * 9;
            #pragma unroll
            for (int kp = 0; kp < 4; kp++) { lt[kp] += pp[kp]; ls[kp] += pp[4 + kp]; }
        }
        // top-2 (first-index tie semantics like jax top_k)
        int i0 = 0; float v0 = lt[0];
        #pragma unroll
        for (int k = 1; k < 4; k++) if (lt[k] > v0) { v0 = lt[k]; i0 = k; }
        int i1 = -1; float v1 = -3.0e38f;
        #pragma unroll
        for (int k = 0; k < 4; k++) if (k != i0 && lt[k] > v1) { v1 = lt[k]; i1 = k; }
        const float e  = __expf(v1 - v0);
        const float s2 = 1.0f / (1.0f + e);
        const float p0 = s2;
        const float p1 = e * s2;
        const float mx = fmaxf(fmaxf(ls[0], ls[1]), fmaxf(ls[2], ls[3]));
        float es[4];
        #pragma unroll
        for (int k = 0; k < 4; k++) es[k] = __expf(ls[k] - mx);
        const float inv = 1.0f / (es[0] + es[1] + es[2] + es[3]);
        const float a = 1.0f / (1.0f + __expf(-__ldg(alpha)));
        #pragma unroll
        for (int k = 0; k < 4; k++) {
            const float hard = (k == i0) ? p0 : ((k == i1) ? p1 : 0.0f);
            sw[tok * 4 + k] = a * hard + (1.0f - a) * (es[k] * inv);
        }
    }
    __syncthreads();

    // ---- Phase C: weighted sum, coalesced; m re-read L2-hot (last touch)
    {
        const float w0 = sw[tokA * 4 + 0];
        const float w1 = sw[tokA * 4 + 1];
        const float w2 = sw[tokA * 4 + 2];
        const float w3 = sw[tokA * 4 + 3];
        const float4* p0_ = reinterpret_cast<const float4*>(m0 + rowOffA);
        const float4* p1_ = reinterpret_cast<const float4*>(m1 + rowOffA);
        const float4* p2_ = reinterpret_cast<const float4*>(m2 + rowOffA);
        const float4* p3_ = reinterpret_cast<const float4*>(m3 + rowOffA);
        float4* po = reinterpret_cast<float4*>(out + rowOffA);
        #pragma unroll 4
        for (int r = 0; r < 16; r++) {
            const int f = jA + 8 * r;
            float4 va = __ldcs(p0_ + f);
            float4 vb = __ldcs(p1_ + f);
            float4 vc = __ldcs(p2_ + f);
            float4 vd = __ldcs(p3_ + f);
            float4 o;
            o.x = w0 * va.x + w1 * vb.x + w2 * vc.x + w3 * vd.x;
            o.y = w0 * va.y + w1 * vb.y + w2 * vc.y + w3 * vd.y;
            o.z = w0 * va.z + w1 * vb.z + w2 * vc.z + w3 * vd.z;
            o.w = w0 * va.w + w1 * vb.w + w2 * vc.w + w3 * vd.w;
            po[f] = o;
        }
    }
}

extern "C" void kernel_launch(void* const* d_in, const int* in_sizes, int n_in,
                              void* d_out, int out_size)
{
    const float* m0    = (const float*)d_in[0];
    const float* m1    = (const float*)d_in[1];
    const float* m2    = (const float*)d_in[2];
    const float* m3    = (const float*)d_in[3];
    const float* W_top = (const float*)d_in[4];
    const float* b_top = (const float*)d_in[5];
    const float* W_sft = (const float*)d_in[6];
    const float* b_sft = (const float*)d_in[7];
    const float* alpha = (const float*)d_in[8];
    float* out = (float*)d_out;

    const int ntok = in_sizes[0] / 512;       // 32768
    const int grid = ntok / TPB_TOK;          // 1024

    cudaFuncSetAttribute(router_kernel,
                         cudaFuncAttributeMaxDynamicSharedMemorySize, SMEM_BYTES);
    router_kernel<<<grid, THREADS, SMEM_BYTES>>>(m0, m1, m2, m3,
                                                 W_top, b_top, W_sft, b_sft,
                                                 alpha, out);
}

// round 7
// speedup vs baseline: 1.3641x; 1.3641x over previous
#include <cuda_runtime.h>
#include <cstdint>
#include <cstddef>

// router_20091857011524: fused 4-way router (GB300 sm_103a) — R7 (= R6 rerun)
// R3 dataflow + cp.async (LDGSTS) double-buffered staging. CHUNK=32 so two
// xs/wsm buffers fit in ~54.5KB smem -> 4 blocks/SM stays. Prefetch lives in
// SMEM via the async engine (R5 showed register prefetch spills under the
// 64-reg cap). One barrier per chunk; copy(c+1) overlaps compute(c).
// (R6 bench was an infra failure; identical design resubmitted.)

#define THREADS 256
#define TPB_TOK 32
#define CHUNK   32
#define NCHUNK  16

// smem float offsets:
//   xs[2]  : each [4 mats][32 tok][36]  = 4608   (stride 36: aligned+conflict-free)
//   wsm[2] : each [32 dims][9] float4   = 1152
//   slog   : [8*32][9]                  = 2304
//   sw     : [32][4]                    =  128
#define XS0_F   0
#define XS1_F   4608
#define W0_F    9216
#define W1_F    10368
#define SLOG_F  11520
#define SW_F    13824
#define SMEM_FLOATS 13952
#define SMEM_BYTES  (SMEM_FLOATS * 4)

__device__ __forceinline__ uint32_t smem_u32(const void* p) {
    uint32_t a;
    asm("{ .reg .u64 t; cvta.to.shared.u64 t, %1; cvt.u32.u64 %0, t; }"
        : "=r"(a) : "l"(p));
    return a;
}
__device__ __forceinline__ void cp16(uint32_t dst, const void* src) {
    asm volatile("cp.async.cg.shared.global [%0], [%1], 16;" :: "r"(dst), "l"(src));
}
__device__ __forceinline__ void cp_commit() {
    asm volatile("cp.async.commit_group;");
}
__device__ __forceinline__ void cp_wait0() {
    asm volatile("cp.async.wait_group 0;" ::: "memory");
}

__global__ __launch_bounds__(THREADS, 4)
void router_kernel(const float* __restrict__ m0, const float* __restrict__ m1,
                   const float* __restrict__ m2, const float* __restrict__ m3,
                   const float* __restrict__ Wt, const float* __restrict__ bt,
                   const float* __restrict__ Ws, const float* __restrict__ bs,
                   const float* __restrict__ alpha, float* __restrict__ out)
{
    extern __shared__ float smem[];
    float* slog = smem + SLOG_F;
    float* sw   = smem + SW_F;
    const uint32_t sbase = smem_u32(smem);

    const int tokBase = blockIdx.x * TPB_TOK;
    const int tid  = threadIdx.x;
    const int lane = tid & 31;
    const int wrp  = tid >> 5;
    const int tokA = tid >> 3;     // 0..31 (staging/phase-C token)
    const int jA   = tid & 7;      // 0..7  (staging/phase-C float4 slot)
    const size_t rowOffA = (size_t)(tokBase + tokA) * 512;

    float acc[8];
    #pragma unroll
    for (int o = 0; o < 8; o++) acc[o] = 0.f;

    // staging addresses (fixed per thread, buffer offset varies)
    const int oW  = tid >> 5;          // 0..7  W out-row
    const int ddW = tid & 31;          // 0..31 W dim-in-chunk
    const float* wRow = (oW < 4) ? (Wt + oW * 2048) : (Ws + (oW - 4) * 2048);
    const uint32_t xsDstBase[2] = {
        sbase + 4u * (XS0_F + tokA * 36 + jA * 4),
        sbase + 4u * (XS1_F + tokA * 36 + jA * 4) };
    const uint32_t wDst[2] = {
        sbase + 4u * (W0_F + (ddW * 9 + oW) * 4),
        sbase + 4u * (W1_F + (ddW * 9 + oW) * 4) };

    const float4* xs4 = reinterpret_cast<const float4*>(smem);
    const float4* wsm4 = reinterpret_cast<const float4*>(smem);

    // ---- issue chunk 0
    {
        const int d0 = 0;
        const uint32_t xd = xsDstBase[0];
        cp16(xd + 4u * (0 * 1152), m0 + rowOffA + d0 + jA * 4);
        cp16(xd + 4u * (1 * 1152), m1 + rowOffA + d0 + jA * 4);
        cp16(xd + 4u * (2 * 1152), m2 + rowOffA + d0 + jA * 4);
        cp16(xd + 4u * (3 * 1152), m3 + rowOffA + d0 + jA * 4);
        cp16(wDst[0], wRow + (d0 + ddW) * 4);
        cp_commit();
    }

    for (int c = 0; c < NCHUNK; c++) {
        const int buf = c & 1;
        cp_wait0();
        __syncthreads();        // chunk c visible to all threads; prior compute done

        // ---- issue chunk c+1 into the other buffer (overlaps compute below)
        if (c + 1 < NCHUNK) {
            const int d1 = (c + 1) * CHUNK;
            const uint32_t xd = xsDstBase[buf ^ 1];
            cp16(xd + 4u * (0 * 1152), m0 + rowOffA + d1 + jA * 4);
            cp16(xd + 4u * (1 * 1152), m1 + rowOffA + d1 + jA * 4);
            cp16(xd + 4u * (2 * 1152), m2 + rowOffA + d1 + jA * 4);
            cp16(xd + 4u * (3 * 1152), m3 + rowOffA + d1 + jA * 4);
            cp16(wDst[buf ^ 1], wRow + (d1 + ddW) * 4);
            cp_commit();
        }

        // ---- compute chunk c: lane = token; warp owns dims [wrp*4, wrp*4+4)
        {
            const int xsF4 = (buf ? XS1_F : XS0_F) >> 2;   // float4 base of xs buf
            const int wF4  = (buf ? W1_F  : W0_F)  >> 2;   // float4 base of w buf
            const int dc   = wrp;                          // float4-group (0..7)
            float4 x0 = xs4[xsF4 + 0 * 288 + lane * 9 + dc];
            float4 x1 = xs4[xsF4 + 1 * 288 + lane * 9 + dc];
            float4 x2 = xs4[xsF4 + 2 * 288 + lane * 9 + dc];
            float4 x3 = xs4[xsF4 + 3 * 288 + lane * 9 + dc];
            const float* xf0 = reinterpret_cast<const float*>(&x0);
            const float* xf1 = reinterpret_cast<const float*>(&x1);
            const float* xf2 = reinterpret_cast<const float*>(&x2);
            const float* xf3 = reinterpret_cast<const float*>(&x3);
            const int dloc = wrp * 4;
            #pragma unroll
            for (int j = 0; j < 4; j++) {
                #pragma unroll
                for (int o = 0; o < 8; o++) {
                    float4 w = wsm4[wF4 + (dloc + j) * 9 + o];  // warp-uniform broadcast
                    acc[o] += xf0[j] * w.x + xf1[j] * w.y + xf2[j] * w.z + xf3[j] * w.w;
                }
            }
        }
        // no trailing barrier: next iteration's wait+bar protects buffer reuse
    }
    __syncthreads();

    // ---- write partial logits, reduce across the 8 warps
    {
        float* sl = slog + (wrp * 32 + lane) * 9;
        #pragma unroll
        for (int o = 0; o < 8; o++) sl[o] = acc[o];
    }
    __syncthreads();

    // ---- per-token epilogue (one lane per token, warp 0)
    if (tid < 32) {
        const int tok = tid;
        float lt[4], ls[4];
        #pragma unroll
        for (int kp = 0; kp < 4; kp++) { lt[kp] = __ldg(bt + kp); ls[kp] = __ldg(bs + kp); }
        #pragma unroll
        for (int w2 = 0; w2 < 8; w2++) {
            const float* pp = slog + (w2 * 32 + tok) * 9;
            #pragma unroll
            for (int kp = 0; kp < 4; kp++) { lt[kp] += pp[kp]; ls[kp] += pp[4 + kp]; }
        }
        // top-2 (first-index tie semantics like jax top_k)
        int i0 = 0; float v0 = lt[0];
        #pragma unroll
        for (int k = 1; k < 4; k++) if (lt[k] > v0) { v0 = lt[k]; i0 = k; }
        int i1 = -1; float v1 = -3.0e38f;
        #pragma unroll
        for (int k = 0; k < 4; k++) if (k != i0 && lt[k] > v1) { v1 = lt[k]; i1 = k; }
        const float e  = __expf(v1 - v0);
        const float s2 = 1.0f / (1.0f + e);
        const float p0 = s2;
        const float p1 = e * s2;
        const float mx = fmaxf(fmaxf(ls[0], ls[1]), fmaxf(ls[2], ls[3]));
        float es[4];
        #pragma unroll
        for (int k = 0; k < 4; k++) es[k] = __expf(ls[k] - mx);
        const float inv = 1.0f / (es[0] + es[1] + es[2] + es[3]);
        const float a = 1.0f / (1.0f + __expf(-__ldg(alpha)));
        #pragma unroll
        for (int k = 0; k < 4; k++) {
            const float hard = (k == i0) ? p0 : ((k == i1) ? p1 : 0.0f);
            sw[tok * 4 + k] = a * hard + (1.0f - a) * (es[k] * inv);
        }
    }
    __syncthreads();

    // ---- Phase C: weighted sum, coalesced; m re-read L2-hot (last touch)
    {
        const float w0 = sw[tokA * 4 + 0];
        const float w1 = sw[tokA * 4 + 1];
        const float w2 = sw[tokA * 4 + 2];
        const float w3 = sw[tokA * 4 + 3];
        const float4* p0_ = reinterpret_cast<const float4*>(m0 + rowOffA);
        const float4* p1_ = reinterpret_cast<const float4*>(m1 + rowOffA);
        const float4* p2_ = reinterpret_cast<const float4*>(m2 + rowOffA);
        const float4* p3_ = reinterpret_cast<const float4*>(m3 + rowOffA);
        float4* po = reinterpret_cast<float4*>(out + rowOffA);
        #pragma unroll 4
        for (int r = 0; r < 16; r++) {
            const int f = jA + 8 * r;
            float4 va = __ldcs(p0_ + f);
            float4 vb = __ldcs(p1_ + f);
            float4 vc = __ldcs(p2_ + f);
            float4 vd = __ldcs(p3_ + f);
            float4 o;
            o.x = w0 * va.x + w1 * vb.x + w2 * vc.x + w3 * vd.x;
            o.y = w0 * va.y + w1 * vb.y + w2 * vc.y + w3 * vd.y;
            o.z = w0 * va.z + w1 * vb.z + w2 * vc.z + w3 * vd.z;
            o.w = w0 * va.w + w1 * vb.w + w2 * vc.w + w3 * vd.w;
            po[f] = o;
        }
    }
}

extern "C" void kernel_launch(void* const* d_in, const int* in_sizes, int n_in,
                              void* d_out, int out_size)
{
    const float* m0    = (const float*)d_in[0];
    const float* m1    = (const float*)d_in[1];
    const float* m2    = (const float*)d_in[2];
    const float* m3    = (const float*)d_in[3];
    const float* W_top = (const float*)d_in[4];
    const float* b_top = (const float*)d_in[5];
    const float* W_sft = (const float*)d_in[6];
    const float* b_sft = (const float*)d_in[7];
    const float* alpha = (const float*)d_in[8];
    float* out = (float*)d_out;

    const int ntok = in_sizes[0] / 512;       // 32768
    const int grid = ntok / TPB_TOK;          // 1024

    cudaFuncSetAttribute(router_kernel,
                         cudaFuncAttributeMaxDynamicSharedMemorySize, SMEM_BYTES);
    router_kernel<<<grid, THREADS, SMEM_BYTES>>>(m0, m1, m2, m3,
                                                 W_top, b_top, W_sft, b_sft,
                                                 alpha, out);
}

// round 8
// speedup vs baseline: 1.4827x; 1.0869x over previous
#include <cuda_runtime.h>
#include <cstdint>
#include <cstddef>

// router_20091857011524: fused 4-way router (GB300 sm_103a) — R8
// Barrier-free warp-autonomous design. Warp owns 4 tokens (lane = t*8+j).
// W staged once to smem as [o][512 f4] with dim permutation f(d)=g*32+jj*8+j
// so the 8 j-lanes read 8 consecutive float4 (conflict-free multicast).
// m streams through a per-warp cp.async ring (depth 3, warp-local waits) —
// no __syncthreads in the main loop; logits reduced via shfl_xor; phase C
// per-warp with short L2 reuse distance.

#define THREADS 256
#define TPB_TOK 32          // 8 warps x 4 tokens
#define NG 16               // 512 dims / 32 dims per group
#define RING_DEPTH 3

// smem floats:
//   Wsm : 8 planes x 512 float4            = 16384 floats (64KB)
//   ring: 8 warps x 3 slots x 512 floats   = 12288 floats (48KB)
#define RING_F 16384
#define SMEM_FLOATS (16384 + 8 * RING_DEPTH * 512)
#define SMEM_BYTES  (SMEM_FLOATS * 4)       // 114688 B

__device__ __forceinline__ uint32_t smem_u32(const void* p) {
    uint32_t a;
    asm("{ .reg .u64 t; cvta.to.shared.u64 t, %1; cvt.u32.u64 %0, t; }"
        : "=r"(a) : "l"(p));
    return a;
}
__device__ __forceinline__ void cp16(uint32_t dst, const void* src) {
    asm volatile("cp.async.cg.shared.global [%0], [%1], 16;" :: "r"(dst), "l"(src));
}
__device__ __forceinline__ void cp_commit() {
    asm volatile("cp.async.commit_group;");
}
__device__ __forceinline__ void cp_wait1() {
    asm volatile("cp.async.wait_group 1;" ::: "memory");
}
__device__ __forceinline__ void cp_wait0() {
    asm volatile("cp.async.wait_group 0;" ::: "memory");
}

__global__ __launch_bounds__(THREADS)
void router_kernel(const float* __restrict__ m0, const float* __restrict__ m1,
                   const float* __restrict__ m2, const float* __restrict__ m3,
                   const float* __restrict__ Wt, const float* __restrict__ bt,
                   const float* __restrict__ Ws, const float* __restrict__ bs,
                   const float* __restrict__ alpha, float* __restrict__ out)
{
    extern __shared__ float smem[];
    float4* wsm = reinterpret_cast<float4*>(smem);
    const uint32_t sbase = smem_u32(smem);

    const int tid  = threadIdx.x;
    const int lane = tid & 31;
    const int wrp  = tid >> 5;
    const int t    = lane >> 3;    // token within warp (0..3)
    const int j    = lane & 7;     // dim slot (0..7)

    // ---- stage W once: Wsm[o*512 + f(d)] = W[o][4 mats of dim d],
    // f(d) = g*32 + jj*8 + jslot  (g=d>>5, jj=d&3, jslot=(d>>2)&7)
    {
        const float4* wt4 = reinterpret_cast<const float4*>(Wt);
        const float4* ws4 = reinterpret_cast<const float4*>(Ws);
        #pragma unroll
        for (int rep = 0; rep < 16; rep++) {
            const int i  = tid + rep * THREADS;   // 0..4095
            const int o  = i >> 9;
            const int dd = i & 511;
            float4 v = (o < 4) ? __ldg(wt4 + o * 512 + dd)
                               : __ldg(ws4 + (o - 4) * 512 + dd);
            const int g = dd >> 5, jj = dd & 3, js = (dd >> 2) & 7;
            wsm[o * 512 + g * 32 + jj * 8 + js] = v;
        }
    }
    __syncthreads();   // the ONLY block barrier

    const int tok = blockIdx.x * TPB_TOK + wrp * 4 + t;
    const size_t row = (size_t)tok * 512;
    const float* mp0 = m0 + row;
    const float* mp1 = m1 + row;
    const float* mp2 = m2 + row;
    const float* mp3 = m3 + row;

    // per-warp ring: slot stride 2048B, mat stride 512B, lane stride 16B
    const uint32_t ringB = sbase + 4u * RING_F + (uint32_t)wrp * (RING_DEPTH * 2048)
                         + (uint32_t)lane * 16u;

    float acc[8];
    #pragma unroll
    for (int o = 0; o < 8; o++) acc[o] = 0.f;

    // ---- prologue: issue g=0,1
    #pragma unroll
    for (int g = 0; g < 2; g++) {
        const int off = g * 32 + j * 4;
        const uint32_t d = ringB + (uint32_t)g * 2048u;
        cp16(d + 0u,    mp0 + off);
        cp16(d + 512u,  mp1 + off);
        cp16(d + 1024u, mp2 + off);
        cp16(d + 1536u, mp3 + off);
        cp_commit();
    }

    // ---- main loop: warp-local pipeline, no barriers
    for (int g = 0; g < NG; g++) {
        if (g + 1 < NG) cp_wait1(); else cp_wait0();

        const uint32_t s = ringB + (uint32_t)(g % RING_DEPTH) * 2048u;
        float4 x0, x1, x2, x3;
        asm volatile("ld.shared.v4.f32 {%0,%1,%2,%3}, [%4];"
            : "=f"(x0.x), "=f"(x0.y), "=f"(x0.z), "=f"(x0.w) : "r"(s + 0u));
        asm volatile("ld.shared.v4.f32 {%0,%1,%2,%3}, [%4];"
            : "=f"(x1.x), "=f"(x1.y), "=f"(x1.z), "=f"(x1.w) : "r"(s + 512u));
        asm volatile("ld.shared.v4.f32 {%0,%1,%2,%3}, [%4];"
            : "=f"(x2.x), "=f"(x2.y), "=f"(x2.z), "=f"(x2.w) : "r"(s + 1024u));
        asm volatile("ld.shared.v4.f32 {%0,%1,%2,%3}, [%4];"
            : "=f"(x3.x), "=f"(x3.y), "=f"(x3.z), "=f"(x3.w) : "r"(s + 1536u));

        // issue g+2 into the freed-up-after-compute... slot (g+2)%3 != g%3 safe:
        // slot (g+2)%3 holds g-1's data (already consumed last iteration).
        if (g + 2 < NG) {
            const int off = (g + 2) * 32 + j * 4;
            const uint32_t d = ringB + (uint32_t)((g + 2) % RING_DEPTH) * 2048u;
            cp16(d + 0u,    mp0 + off);
            cp16(d + 512u,  mp1 + off);
            cp16(d + 1024u, mp2 + off);
            cp16(d + 1536u, mp3 + off);
            cp_commit();
        }

        const float xf0[4] = {x0.x, x0.y, x0.z, x0.w};
        const float xf1[4] = {x1.x, x1.y, x1.z, x1.w};
        const float xf2[4] = {x2.x, x2.y, x2.z, x2.w};
        const float xf3[4] = {x3.x, x3.y, x3.z, x3.w};
        #pragma unroll
        for (int jj = 0; jj < 4; jj++) {
            #pragma unroll
            for (int o = 0; o < 8; o++) {
                float4 w = wsm[o * 512 + g * 32 + jj * 8 + j];  // conflict-free multicast
                acc[o] += xf0[jj] * w.x + xf1[jj] * w.y + xf2[jj] * w.z + xf3[jj] * w.w;
            }
        }
    }

    // ---- reduce over the 8 j-lanes (butterfly: every lane gets full sums)
    #pragma unroll
    for (int m = 1; m < 8; m <<= 1) {
        #pragma unroll
        for (int o = 0; o < 8; o++)
            acc[o] += __shfl_xor_sync(0xffffffffu, acc[o], m);
    }

    // ---- per-token epilogue (redundant across the 8 j-lanes, no divergence)
    float w[4];
    {
        float lt[4], ls[4];
        #pragma unroll
        for (int kp = 0; kp < 4; kp++) {
            lt[kp] = acc[kp]     + __ldg(bt + kp);
            ls[kp] = acc[4 + kp] + __ldg(bs + kp);
        }
        // top-2 (first-index tie semantics like jax top_k)
        int i0 = 0; float v0 = lt[0];
        #pragma unroll
        for (int k = 1; k < 4; k++) if (lt[k] > v0) { v0 = lt[k]; i0 = k; }
        int i1 = -1; float v1 = -3.0e38f;
        #pragma unroll
        for (int k = 0; k < 4; k++) if (k != i0 && lt[k] > v1) { v1 = lt[k]; i1 = k; }
        const float e  = __expf(v1 - v0);
        const float s2 = 1.0f / (1.0f + e);
        const float p0 = s2;
        const float p1 = e * s2;
        const float mx = fmaxf(fmaxf(ls[0], ls[1]), fmaxf(ls[2], ls[3]));
        float es[4];
        #pragma unroll
        for (int k = 0; k < 4; k++) es[k] = __expf(ls[k] - mx);
        const float inv = 1.0f / (es[0] + es[1] + es[2] + es[3]);
        const float a = 1.0f / (1.0f + __expf(-__ldg(alpha)));
        #pragma unroll
        for (int k = 0; k < 4; k++) {
            const float hard = (k == i0) ? p0 : ((k == i1) ? p1 : 0.0f);
            w[k] = a * hard + (1.0f - a) * (es[k] * inv);
        }
    }

    // ---- phase C: weighted sum for this lane's token; L2-hot re-read
    {
        const float4* p0_ = reinterpret_cast<const float4*>(mp0);
        const float4* p1_ = reinterpret_cast<const float4*>(mp1);
        const float4* p2_ = reinterpret_cast<const float4*>(mp2);
        const float4* p3_ = reinterpret_cast<const float4*>(mp3);
        float4* po = reinterpret_cast<float4*>(out + row);
        #pragma unroll 4
        for (int r = 0; r < 16; r++) {
            const int f = j + 8 * r;    // 8 lanes -> 128B contiguous per row
            float4 va = __ldcs(p0_ + f);
            float4 vb = __ldcs(p1_ + f);
            float4 vc = __ldcs(p2_ + f);
            float4 vd = __ldcs(p3_ + f);
            float4 o4;
            o4.x = w[0] * va.x + w[1] * vb.x + w[2] * vc.x + w[3] * vd.x;
            o4.y = w[0] * va.y + w[1] * vb.y + w[2] * vc.y + w[3] * vd.y;
            o4.z = w[0] * va.z + w[1] * vb.z + w[2] * vc.z + w[3] * vd.z;
            o4.w = w[0] * va.w + w[1] * vb.w + w[2] * vc.w + w[3] * vd.w;
            po[f] = o4;
        }
    }
}

extern "C" void kernel_launch(void* const* d_in, const int* in_sizes, int n_in,
                              void* d_out, int out_size)
{
    const float* m0    = (const float*)d_in[0];
    const float* m1    = (const float*)d_in[1];
    const float* m2    = (const float*)d_in[2];
    const float* m3    = (const float*)d_in[3];
    const float* W_top = (const float*)d_in[4];
    const float* b_top = (const float*)d_in[5];
    const float* W_sft = (const float*)d_in[6];
    const float* b_sft = (const float*)d_in[7];
    const float* alpha = (const float*)d_in[8];
    float* out = (float*)d_out;

    const int ntok = in_sizes[0] / 512;       // 32768
    const int grid = ntok / TPB_TOK;          // 1024

    cudaFuncSetAttribute(router_kernel,
                         cudaFuncAttributeMaxDynamicSharedMemorySize, SMEM_BYTES);
    router_kernel<<<grid, THREADS, SMEM_BYTES>>>(m0, m1, m2, m3,
                                                 W_top, b_top, W_sft, b_sft,
                                                 alpha, out);
}